// round 10
// baseline (speedup 1.0000x reference)
#include <cuda_runtime.h>

// BSplineTransformation: x (16,3,1024,1024) f32, control_points (1,2,35,35) f32
// out = concat(transformed (16,3,1024,1024), deformation_field (2,1024,1024))

#define HH 1024
#define WW 1024
#define NPIX (HH*WW)
#define NB 16
#define NC 3
#define NIMG (NB*NC)
#define CP 35
#define CP2 (CP*CP)

// Block = 32x8 pixel tile: lane -> x, warp -> y. Vertical neighbors share input
// rows within the block -> L1 hits on ~half the gather loads.

__global__ __launch_bounds__(256) void bspline_kernel(
    const float* __restrict__ x,
    const float* __restrict__ cp,
    float* __restrict__ out)
{
    __shared__ float scp[2*CP2];
    for (int t = threadIdx.x; t < 2*CP2; t += 256) scp[t] = cp[t];
    __syncthreads();

    const int lane = threadIdx.x & 31;
    const int wrp  = threadIdx.x >> 5;
    const int tx   = blockIdx.x & 31;        // 32 x-tiles
    const int ty   = blockIdx.x >> 5;        // 128 y-tiles
    const int i = ty * 8 + wrp;              // pixel row
    const int j = tx * 32 + lane;            // pixel col
    const int p = (i << 10) + j;

    const float gy = fmaf((float)i, 2.0f / 1023.0f, -1.0f);
    const float gx = fmaf((float)j, 2.0f / 1023.0f, -1.0f);

    // ---- deformation field: grid_sample(control_points, border, align_corners) ----
    const float cx = (gx + 1.0f) * 17.0f;
    const float cy = (gy + 1.0f) * 17.0f;
    float icx = fminf(fmaxf((cx + 1.0f) * 17.0f, 0.0f), 34.0f);
    float icy = fminf(fmaxf((cy + 1.0f) * 17.0f, 0.0f), 34.0f);
    const float fcx = floorf(icx);
    const float fcy = floorf(icy);
    const int cx0 = (int)fcx;
    const int cy0 = (int)fcy;
    const int cx1 = min(cx0 + 1, CP - 1);
    const int cy1 = min(cy0 + 1, CP - 1);
    const float wx = icx - fcx;
    const float wy = icy - fcy;

    const int o00 = cy0 * CP + cx0;
    const int o01 = cy0 * CP + cx1;
    const int o10 = cy1 * CP + cx0;
    const int o11 = cy1 * CP + cx1;

    const float t0 = fmaf(wx, scp[o01] - scp[o00], scp[o00]);
    const float b0 = fmaf(wx, scp[o11] - scp[o10], scp[o10]);
    const float d0 = fmaf(wy, b0 - t0, t0);
    const float t1 = fmaf(wx, scp[CP2+o01] - scp[CP2+o00], scp[CP2+o00]);
    const float b1 = fmaf(wx, scp[CP2+o11] - scp[CP2+o10], scp[CP2+o10]);
    const float d1 = fmaf(wy, b1 - t1, t1);

    // deformation field output (once per pixel)
    {
        float* def = out + (long long)NIMG * NPIX;
        def[p]        = d0;
        def[NPIX + p] = d1;
    }

    // ---- main sample coords (shared by all 48 images) ----
    float sx = fminf(fmaxf((gx + d1 + 1.0f) * 511.5f, 0.0f), 1023.0f);
    float sy = fminf(fmaxf((gy + d0 + 1.0f) * 511.5f, 0.0f), 1023.0f);
    const float fsx = floorf(sx);
    const float fsy = floorf(sy);
    const int ix0 = (int)fsx;
    const int iy0 = (int)fsy;
    const int ix1 = min(ix0 + 1, WW - 1);
    const int iy1 = min(iy0 + 1, HH - 1);
    const float ax = sx - fsx;
    const float ay = sy - fsy;

    const int q00 = (iy0 << 10) + ix0;
    const int q01 = (iy0 << 10) + ix1;
    const int q10 = (iy1 << 10) + ix0;
    const int q11 = (iy1 << 10) + ix1;

    // ---- 48 images, pointer-bump loop ----
    const float* im = x;
    float*       ob = out + p;

    #pragma unroll
    for (int m = 0; m < NIMG; m++) {
        const float v00 = __ldg(im + q00);
        const float v01 = __ldg(im + q01);
        const float v10 = __ldg(im + q10);
        const float v11 = __ldg(im + q11);
        const float top = fmaf(ax, v01 - v00, v00);
        const float bot = fmaf(ax, v11 - v10, v10);
        *ob = fmaf(ay, bot - top, top);
        im += NPIX;
        ob += NPIX;
    }
}

extern "C" void kernel_launch(void* const* d_in, const int* in_sizes, int n_in,
                              void* d_out, int out_size)
{
    const float* x  = (const float*)d_in[0];
    const float* cp = (const float*)d_in[1];
    float* out = (float*)d_out;

    bspline_kernel<<<NPIX / 256, 256>>>(x, cp, out);
}